// round 3
// baseline (speedup 1.0000x reference)
#include <cuda_runtime.h>

#define NROW 4096
#define NLVL 10   // levels 0..9 accumulated; level 10 is trivial (H_all=N, H_pos=N_pos)

__device__ float g_ap[NROW];
__device__ float g_valid[NROW];

__global__ __launch_bounds__(256) void fastap_row_kernel(
    const float* __restrict__ batch, const float* __restrict__ labels)
{
    const int row = blockIdx.x;
    const float4* b4 = reinterpret_cast<const float4*>(batch + (size_t)row * NROW);
    const float4* l4 = reinterpret_cast<const float4*>(labels + (size_t)row * NROW);

    float accA[NLVL], accP[NLVL];
    #pragma unroll
    for (int l = 0; l < NLVL; l++) { accA[l] = 0.f; accP[l] = 0.f; }
    float npos = 0.f;

    // NROW/4 = 1024 float4s, 256 threads -> exactly 4 iterations per thread
    for (int it = threadIdx.x; it < NROW / 4; it += 256) {
        float4 xv = b4[it];
        float4 lv = l4[it];
        float xs[4] = {xv.x, xv.y, xv.z, xv.w};
        float ls[4] = {lv.x, lv.y, lv.z, lv.w};
        #pragma unroll
        for (int e = 0; e < 4; e++) {
            // t = dist2/Delta = (2 - 2*clip(x,-1,1)) / 0.4 = 5 - 5x, with per-level
            // saturation making the explicit [0,10] clamp redundant.
            float t = fmaf(-5.0f, xs[e], 5.0f);
            float u[NLVL];
            #pragma unroll
            for (int l = 0; l < NLVL; l++) {
                u[l] = __saturatef((float)(l + 1) - t);  // FADD.SAT
                accA[l] += u[l];
            }
            float lbl = ls[e];
            npos += lbl;
            // labels are exactly 0.0/1.0; skip pos accumulation if whole warp is 0
            if (__any_sync(0xffffffffu, lbl > 0.0f)) {
                #pragma unroll
                for (int l = 0; l < NLVL; l++) accP[l] += lbl * u[l];
            }
        }
    }

    // ---- block reduction of 21 scalars ----
    __shared__ float red[8][21];
    float vals[21];
    #pragma unroll
    for (int l = 0; l < NLVL; l++) { vals[l] = accA[l]; vals[10 + l] = accP[l]; }
    vals[20] = npos;

    #pragma unroll
    for (int k = 0; k < 21; k++) {
        float v = vals[k];
        #pragma unroll
        for (int o = 16; o > 0; o >>= 1) v += __shfl_down_sync(0xffffffffu, v, o);
        vals[k] = v;
    }
    int warp = threadIdx.x >> 5;
    int lane = threadIdx.x & 31;
    if (lane == 0) {
        #pragma unroll
        for (int k = 0; k < 21; k++) red[warp][k] = vals[k];
    }
    __syncthreads();
    if (threadIdx.x < 21) {
        float s = 0.f;
        #pragma unroll
        for (int w = 0; w < 8; w++) s += red[w][threadIdx.x];
        red[0][threadIdx.x] = s;
    }
    __syncthreads();

    if (threadIdx.x == 0) {
        float totA[NLVL + 1], totP[NLVL + 1];
        #pragma unroll
        for (int l = 0; l < NLVL; l++) { totA[l] = red[0][l]; totP[l] = red[0][10 + l]; }
        float np = red[0][20];
        totA[NLVL] = (float)NROW;   // every t contributes 1 at level 10
        totP[NLVL] = np;

        float apsum = 0.f, prev = 0.f;
        #pragma unroll
        for (int l = 0; l <= NLVL; l++) {
            float h = totP[l] - prev;               // h_pos[l]
            if (totA[l] > 0.f) apsum += h * totP[l] / totA[l];
            prev = totP[l];
        }
        bool valid = (np > 0.f);
        g_ap[row]    = valid ? (apsum / np) : 0.f;
        g_valid[row] = valid ? 1.f : 0.f;
    }
}

__global__ __launch_bounds__(256) void fastap_finalize(float* __restrict__ out)
{
    __shared__ float sa[8], sv[8];
    float a = 0.f, v = 0.f;
    for (int i = threadIdx.x; i < NROW; i += 256) {
        a += g_ap[i];
        v += g_valid[i];
    }
    #pragma unroll
    for (int o = 16; o > 0; o >>= 1) {
        a += __shfl_down_sync(0xffffffffu, a, o);
        v += __shfl_down_sync(0xffffffffu, v, o);
    }
    int warp = threadIdx.x >> 5;
    int lane = threadIdx.x & 31;
    if (lane == 0) { sa[warp] = a; sv[warp] = v; }
    __syncthreads();
    if (threadIdx.x == 0) {
        float ta = 0.f, tv = 0.f;
        #pragma unroll
        for (int w = 0; w < 8; w++) { ta += sa[w]; tv += sv[w]; }
        out[0] = 1.0f - ta / tv;
    }
}

extern "C" void kernel_launch(void* const* d_in, const int* in_sizes, int n_in,
                              void* d_out, int out_size)
{
    const float* batch  = (const float*)d_in[0];
    const float* labels = (const float*)d_in[1];
    fastap_row_kernel<<<NROW, 256>>>(batch, labels);
    fastap_finalize<<<1, 256>>>((float*)d_out);
}

// round 4
// speedup vs baseline: 1.1404x; 1.1404x over previous
#include <cuda_runtime.h>
#include <cstdint>

#define NROW 4096
#define NLVL 10   // levels L=0..9; level 10 is trivial (H_all=N, H_pos=N_pos)
#define TPB  256

__device__ float g_acc_a = 0.f;
__device__ float g_acc_v = 0.f;
__device__ unsigned int g_cnt = 0u;

// u = sat(x*5 + addend)  -- FFMA with immediate multiplier (rt=1) + SAT
__device__ __forceinline__ float ffma_sat5(float x, float addend) {
    float u;
    asm("fma.rn.sat.f32 %0, %1, 0f40A00000, %2;" : "=f"(u) : "f"(x), "f"(addend));
    return u;
}
// acc = u*1.0 + acc  -- FFMA-imm (rt=1), numerically identical to FADD
__device__ __forceinline__ void facc1(float& acc, float u) {
    asm("fma.rn.f32 %0, %1, 0f3F800000, %0;" : "+f"(acc) : "f"(u));
}
__device__ __forceinline__ unsigned long long pack2(float lo, float hi) {
    unsigned long long v;
    asm("mov.b64 %0, {%1, %2};" : "=l"(v) : "r"(__float_as_uint(lo)), "r"(__float_as_uint(hi)));
    return v;
}
__device__ __forceinline__ void unpack2(unsigned long long v, float& lo, float& hi) {
    unsigned a, b;
    asm("mov.b64 {%0, %1}, %2;" : "=r"(a), "=r"(b) : "l"(v));
    lo = __uint_as_float(a); hi = __uint_as_float(b);
}
__device__ __forceinline__ void fma2acc(unsigned long long& acc, unsigned long long u2,
                                        unsigned long long m2) {
    asm("fma.rn.f32x2 %0, %1, %2, %0;" : "+l"(acc) : "l"(u2), "l"(m2));
}

__global__ __launch_bounds__(TPB) void fastap_fused(
    const float* __restrict__ batch, const float* __restrict__ labels,
    float* __restrict__ out)
{
    const int row = blockIdx.x;
    const float4* b4 = reinterpret_cast<const float4*>(batch + (size_t)row * NROW);
    const float4* l4 = reinterpret_cast<const float4*>(labels + (size_t)row * NROW);

    float accA[NLVL];
    unsigned long long accP2[NLVL / 2];
    #pragma unroll
    for (int l = 0; l < NLVL; l++) accA[l] = 0.f;
    #pragma unroll
    for (int p = 0; p < NLVL / 2; p++) accP2[p] = pack2(0.f, 0.f);
    int npos = 0;

    // NROW/4 = 1024 float4s, 256 threads -> exactly 4 iterations, fully unrolled
    #pragma unroll
    for (int j = 0; j < 4; j++) {
        const int it = threadIdx.x + j * TPB;
        float4 xv = b4[it];
        float4 lv = l4[it];
        float xs[4] = {xv.x, xv.y, xv.z, xv.w};
        float ls[4] = {lv.x, lv.y, lv.z, lv.w};
        #pragma unroll
        for (int e = 0; e < 4; e++) {
            const float x = xs[e];
            float u[NLVL];
            // t = 5 - 5x in [0,10]; u[L] = clamp((L+1) - t, 0, 1) = sat(5x + (L-4))
            #pragma unroll
            for (int l = 0; l < NLVL; l++) {
                u[l] = ffma_sat5(x, (float)(l - 4));
                facc1(accA[l], u[l]);
            }
            const float lbl = ls[e];
            const bool pos = (lbl != 0.f);
            npos += pos ? 1 : 0;
            // labels are exactly 0/1; skip pos path when the whole warp is 0
            if (__any_sync(0xffffffffu, pos)) {
                unsigned long long lbl2 = pack2(lbl, lbl);
                #pragma unroll
                for (int p = 0; p < NLVL / 2; p++) {
                    unsigned long long u2 = pack2(u[2 * p], u[2 * p + 1]);
                    fma2acc(accP2[p], u2, lbl2);
                }
            }
        }
    }

    // ---- block reduction of 20 floats + 1 int ----
    float vals[20];
    #pragma unroll
    for (int l = 0; l < NLVL; l++) vals[l] = accA[l];
    #pragma unroll
    for (int p = 0; p < NLVL / 2; p++) unpack2(accP2[p], vals[10 + 2 * p], vals[10 + 2 * p + 1]);

    #pragma unroll
    for (int k = 0; k < 20; k++) {
        float v = vals[k];
        #pragma unroll
        for (int o = 16; o > 0; o >>= 1) v += __shfl_down_sync(0xffffffffu, v, o);
        vals[k] = v;
    }
    {
        int v = npos;
        #pragma unroll
        for (int o = 16; o > 0; o >>= 1) v += __shfl_down_sync(0xffffffffu, v, o);
        npos = v;
    }

    __shared__ float red[8][21];
    const int warp = threadIdx.x >> 5;
    const int lane = threadIdx.x & 31;
    if (lane == 0) {
        #pragma unroll
        for (int k = 0; k < 20; k++) red[warp][k] = vals[k];
        red[warp][20] = (float)npos;
    }
    __syncthreads();

    if (threadIdx.x == 0) {
        float tot[21];
        #pragma unroll
        for (int k = 0; k < 21; k++) {
            float s = 0.f;
            #pragma unroll
            for (int w = 0; w < 8; w++) s += red[w][k];
            tot[k] = s;
        }
        float totA[NLVL + 1], totP[NLVL + 1];
        #pragma unroll
        for (int l = 0; l < NLVL; l++) { totA[l] = tot[l]; totP[l] = tot[10 + l]; }
        const float np = tot[20];
        totA[NLVL] = (float)NROW;   // every t contributes 1 at level 10
        totP[NLVL] = np;

        float apsum = 0.f, prev = 0.f;
        #pragma unroll
        for (int l = 0; l <= NLVL; l++) {
            float h = totP[l] - prev;               // h_pos[l]
            if (totA[l] > 0.f) apsum += h * totP[l] / totA[l];
            prev = totP[l];
        }
        const bool valid = (np > 0.f);
        const float ap = valid ? (apsum / np) : 0.f;

        // ---- fused finalize: last block computes the scalar loss ----
        atomicAdd(&g_acc_a, ap);
        atomicAdd(&g_acc_v, valid ? 1.f : 0.f);
        __threadfence();
        const unsigned arrived = atomicAdd(&g_cnt, 1u);
        if (arrived == NROW - 1) {
            const float ta = *(volatile float*)&g_acc_a;
            const float tv = *(volatile float*)&g_acc_v;
            out[0] = 1.0f - ta / tv;
            // reset for the next graph replay (visible at next launch boundary)
            g_acc_a = 0.f;
            g_acc_v = 0.f;
            g_cnt = 0u;
        }
    }
}

extern "C" void kernel_launch(void* const* d_in, const int* in_sizes, int n_in,
                              void* d_out, int out_size)
{
    const float* batch  = (const float*)d_in[0];
    const float* labels = (const float*)d_in[1];
    fastap_fused<<<NROW, TPB>>>(batch, labels, (float*)d_out);
}

// round 5
// speedup vs baseline: 1.2074x; 1.0587x over previous
#include <cuda_runtime.h>

#define NROW 4096
#define NLVL 10   // levels L=0..9; level 10 is trivial (H_all=N, H_pos=N_pos)
#define TPB  512
#define EPT  2    // float4-pairs per thread: TPB*EPT*4 = 4096
#define NWARP (TPB / 32)

__device__ float g_acc_a = 0.f;
__device__ float g_acc_v = 0.f;
__device__ unsigned int g_cnt = 0u;

// u = sat(x*5 + addend)  -- FFMA with immediate multiplier (rt=1) + SAT
__device__ __forceinline__ float ffma_sat5(float x, float addend) {
    float u;
    asm("fma.rn.sat.f32 %0, %1, 0f40A00000, %2;" : "=f"(u) : "f"(x), "f"(addend));
    return u;
}
// acc = u*1.0 + acc  -- FFMA-imm (rt=1), numerically identical to FADD
__device__ __forceinline__ void facc1(float& acc, float u) {
    asm("fma.rn.f32 %0, %1, 0f3F800000, %0;" : "+f"(acc) : "f"(u));
}

__global__ __launch_bounds__(TPB) void fastap_fused(
    const float* __restrict__ batch, const float* __restrict__ labels,
    float* __restrict__ out)
{
    const int row  = blockIdx.x;
    const int lane = threadIdx.x & 31;
    const int warp = threadIdx.x >> 5;
    const float4* b4 = reinterpret_cast<const float4*>(batch  + (size_t)row * NROW);
    const float4* l4 = reinterpret_cast<const float4*>(labels + (size_t)row * NROW);

    // front-batch all loads (streaming: no reuse across blocks)
    float4 xv[EPT], lv[EPT];
    #pragma unroll
    for (int j = 0; j < EPT; j++) {
        xv[j] = __ldcs(&b4[threadIdx.x + j * TPB]);
        lv[j] = __ldcs(&l4[threadIdx.x + j * TPB]);
    }

    float accA[NLVL];
    #pragma unroll
    for (int l = 0; l < NLVL; l++) accA[l] = 0.f;
    float accP = 0.f;                       // lane L (<10) holds warp-total H_pos level L
    float npos = 0.f;                       // identical on all lanes of the warp
    const float lvladd = (float)(lane - 4); // addend for this lane's owned level

    #pragma unroll
    for (int j = 0; j < EPT; j++) {
        float xs[4] = {xv[j].x, xv[j].y, xv[j].z, xv[j].w};
        float ls[4] = {lv[j].x, lv[j].y, lv[j].z, lv[j].w};
        #pragma unroll
        for (int e = 0; e < 4; e++) {
            const float x = xs[e];
            // cumulative soft histogram: u[L] = clamp((L+1)-t, 0, 1) = sat(5x + (L-4))
            #pragma unroll
            for (int l = 0; l < NLVL; l++) {
                float u = ffma_sat5(x, (float)(l - 4));
                facc1(accA[l], u);
            }
            // positives are ~1/64 dense: process per set bit, distributed across lanes
            unsigned m = __ballot_sync(0xffffffffu, ls[e] != 0.0f);
            npos += (float)__popc(m);
            while (m) {
                const int src = __ffs(m) - 1;
                m &= m - 1u;
                const float xb = __shfl_sync(0xffffffffu, x, src);
                const float u  = ffma_sat5(xb, lvladd);
                if (lane < NLVL) facc1(accP, u);
            }
        }
    }

    // ---- intra-warp reduce accA (accP/npos already warp-level) ----
    #pragma unroll
    for (int l = 0; l < NLVL; l++) {
        float v = accA[l];
        #pragma unroll
        for (int o = 16; o > 0; o >>= 1) v += __shfl_down_sync(0xffffffffu, v, o);
        accA[l] = v;            // valid on lane 0
    }

    __shared__ float red[NWARP][21];
    __shared__ float tot[21];
    if (lane < NLVL) red[warp][10 + lane] = accP;
    if (lane == 0) {
        #pragma unroll
        for (int l = 0; l < NLVL; l++) red[warp][l] = accA[l];
        red[warp][20] = npos;
    }
    __syncthreads();

    if (threadIdx.x < 21) {
        float s = 0.f;
        #pragma unroll
        for (int w = 0; w < NWARP; w++) s += red[w][threadIdx.x];
        tot[threadIdx.x] = s;
    }
    __syncthreads();

    if (threadIdx.x == 0) {
        float totA[NLVL + 1], totP[NLVL + 1];
        #pragma unroll
        for (int l = 0; l < NLVL; l++) { totA[l] = tot[l]; totP[l] = tot[10 + l]; }
        const float np = tot[20];
        totA[NLVL] = (float)NROW;   // every element contributes 1 at level 10
        totP[NLVL] = np;

        float apsum = 0.f, prev = 0.f;
        #pragma unroll
        for (int l = 0; l <= NLVL; l++) {
            float h = totP[l] - prev;               // h_pos[l]
            if (totA[l] > 0.f) apsum += h * totP[l] / totA[l];
            prev = totP[l];
        }
        const bool valid = (np > 0.f);
        const float ap = valid ? (apsum / np) : 0.f;

        // ---- fused finalize: last-arriving block computes the scalar loss ----
        atomicAdd(&g_acc_a, ap);
        atomicAdd(&g_acc_v, valid ? 1.f : 0.f);
        __threadfence();
        const unsigned arrived = atomicAdd(&g_cnt, 1u);
        if (arrived == NROW - 1) {
            const float ta = *(volatile float*)&g_acc_a;
            const float tv = *(volatile float*)&g_acc_v;
            out[0] = 1.0f - ta / tv;
            // reset for the next graph replay
            g_acc_a = 0.f;
            g_acc_v = 0.f;
            g_cnt = 0u;
        }
    }
}

extern "C" void kernel_launch(void* const* d_in, const int* in_sizes, int n_in,
                              void* d_out, int out_size)
{
    const float* batch  = (const float*)d_in[0];
    const float* labels = (const float*)d_in[1];
    fastap_fused<<<NROW, TPB>>>(batch, labels, (float*)d_out);
}

// round 6
// speedup vs baseline: 1.3182x; 1.0917x over previous
#include <cuda_runtime.h>

#define NROW 4096
#define NLVL 10   // levels L=0..9; level 10 is trivial (H_all=N, H_pos=N_pos)
#define TPB  256
#define EPT  4    // float4 per array per thread: TPB*EPT*4 = 4096
#define NWARP (TPB / 32)

__device__ float g_acc_a = 0.f;
__device__ float g_acc_v = 0.f;
__device__ unsigned int g_cnt = 0u;

// u = sat(x*5 + addend)  -- FFMA with immediate multiplier (rt=1) + SAT
__device__ __forceinline__ float ffma_sat5(float x, float addend) {
    float u;
    asm("fma.rn.sat.f32 %0, %1, 0f40A00000, %2;" : "=f"(u) : "f"(x), "f"(addend));
    return u;
}
// acc = u*1.0 + acc  -- FFMA-imm (rt=1), numerically identical to FADD
__device__ __forceinline__ void facc1(float& acc, float u) {
    asm("fma.rn.f32 %0, %1, 0f3F800000, %0;" : "+f"(acc) : "f"(u));
}

__global__ __launch_bounds__(TPB) void fastap_fused(
    const float* __restrict__ batch, const float* __restrict__ labels,
    float* __restrict__ out)
{
    const int row  = blockIdx.x;
    const int lane = threadIdx.x & 31;
    const int warp = threadIdx.x >> 5;
    const float4* b4 = reinterpret_cast<const float4*>(batch  + (size_t)row * NROW);
    const float4* l4 = reinterpret_cast<const float4*>(labels + (size_t)row * NROW);

    // front-batch ALL loads (streaming, no reuse) -> 8 LDG.128 in flight
    float4 xv[EPT], lv[EPT];
    #pragma unroll
    for (int j = 0; j < EPT; j++) xv[j] = __ldcs(&b4[threadIdx.x + j * TPB]);
    #pragma unroll
    for (int j = 0; j < EPT; j++) lv[j] = __ldcs(&l4[threadIdx.x + j * TPB]);

    float accA[NLVL];
    #pragma unroll
    for (int l = 0; l < NLVL; l++) accA[l] = 0.f;
    float accP = 0.f;                       // lane L (<10) holds warp-total H_pos level L
    int   npos = 0;                         // identical on all lanes (from popc)
    const float lvladd = (float)(lane - 4); // addend for this lane's owned level

    #pragma unroll
    for (int j = 0; j < EPT; j++) {
        float xs[4] = {xv[j].x, xv[j].y, xv[j].z, xv[j].w};
        float ls[4] = {lv[j].x, lv[j].y, lv[j].z, lv[j].w};
        #pragma unroll
        for (int e = 0; e < 4; e++) {
            const float x = xs[e];
            // cumulative soft histogram: u[L] = clamp((L+1)-t, 0, 1) = sat(5x + (L-4))
            #pragma unroll
            for (int l = 0; l < NLVL; l++) {
                float u = ffma_sat5(x, (float)(l - 4));
                facc1(accA[l], u);
            }
            // positives ~1/64 dense: handle per set bit, one histogram level per lane
            unsigned m = __ballot_sync(0xffffffffu, ls[e] != 0.0f);
            npos += __popc(m);
            while (m) {
                const int src = __ffs(m) - 1;
                m &= m - 1u;
                const float xb = __shfl_sync(0xffffffffu, x, src);
                const float u  = ffma_sat5(xb, lvladd);
                if (lane < NLVL) facc1(accP, u);
            }
        }
    }

    // ---- intra-warp reduce accA (accP/npos already warp-level) ----
    #pragma unroll
    for (int l = 0; l < NLVL; l++) {
        float v = accA[l];
        #pragma unroll
        for (int o = 16; o > 0; o >>= 1) v += __shfl_down_sync(0xffffffffu, v, o);
        accA[l] = v;            // valid on lane 0
    }

    __shared__ float red[NWARP][21];
    __shared__ float tot[21];
    if (lane < NLVL) red[warp][10 + lane] = accP;
    if (lane == 0) {
        #pragma unroll
        for (int l = 0; l < NLVL; l++) red[warp][l] = accA[l];
        red[warp][20] = (float)npos;
    }
    __syncthreads();

    if (threadIdx.x < 21) {
        float s = 0.f;
        #pragma unroll
        for (int w = 0; w < NWARP; w++) s += red[w][threadIdx.x];
        tot[threadIdx.x] = s;
    }
    __syncthreads();

    if (threadIdx.x == 0) {
        float totA[NLVL + 1], totP[NLVL + 1];
        #pragma unroll
        for (int l = 0; l < NLVL; l++) { totA[l] = tot[l]; totP[l] = tot[10 + l]; }
        const float np = tot[20];
        totA[NLVL] = (float)NROW;   // every element contributes 1 at level 10
        totP[NLVL] = np;

        float apsum = 0.f, prev = 0.f;
        #pragma unroll
        for (int l = 0; l <= NLVL; l++) {
            float h = totP[l] - prev;               // h_pos[l]
            if (totA[l] > 0.f) apsum += h * totP[l] / totA[l];
            prev = totP[l];
        }
        const bool valid = (np > 0.f);
        const float ap = valid ? (apsum / np) : 0.f;

        // ---- fused finalize: last-arriving block computes the scalar loss ----
        atomicAdd(&g_acc_a, ap);
        atomicAdd(&g_acc_v, valid ? 1.f : 0.f);
        __threadfence();
        const unsigned arrived = atomicAdd(&g_cnt, 1u);
        if (arrived == NROW - 1) {
            const float ta = *(volatile float*)&g_acc_a;
            const float tv = *(volatile float*)&g_acc_v;
            out[0] = 1.0f - ta / tv;
            // reset for the next graph replay
            g_acc_a = 0.f;
            g_acc_v = 0.f;
            g_cnt = 0u;
        }
    }
}

extern "C" void kernel_launch(void* const* d_in, const int* in_sizes, int n_in,
                              void* d_out, int out_size)
{
    const float* batch  = (const float*)d_in[0];
    const float* labels = (const float*)d_in[1];
    fastap_fused<<<NROW, TPB>>>(batch, labels, (float*)d_out);
}

// round 7
// speedup vs baseline: 1.5541x; 1.1789x over previous
#include <cuda_runtime.h>

#define NROW 4096
#define NLVL 10   // levels L=0..9; level 10 is trivial (H_all=N, H_pos=N_pos)
#define TPB  256
#define EPT  4    // float4 per array per thread: TPB*EPT*4 = 4096
#define NWARP (TPB / 32)

__device__ float g_acc_a = 0.f;
__device__ float g_acc_v = 0.f;
__device__ unsigned int g_cnt = 0u;

// u = sat(x*5 + addend)  -- FFMA with immediate multiplier (rt=1) + SAT
__device__ __forceinline__ float ffma_sat5(float x, float addend) {
    float u;
    asm("fma.rn.sat.f32 %0, %1, 0f40A00000, %2;" : "=f"(u) : "f"(x), "f"(addend));
    return u;
}
// acc = u*1.0 + acc  -- FFMA-imm (rt=1), numerically identical to FADD
__device__ __forceinline__ void facc1(float& acc, float u) {
    asm("fma.rn.f32 %0, %1, 0f3F800000, %0;" : "+f"(acc) : "f"(u));
}

__global__ __launch_bounds__(TPB, 6) void fastap_fused(
    const float* __restrict__ batch, const float* __restrict__ labels,
    float* __restrict__ out)
{
    const int tid  = threadIdx.x;
    const int lane = tid & 31;
    const int warp = tid >> 5;
    const int row  = blockIdx.x;
    const float4* b4 = reinterpret_cast<const float4*>(batch  + (size_t)row * NROW);
    const float4* l4 = reinterpret_cast<const float4*>(labels + (size_t)row * NROW);

    // front-batch all 8 LDG.128
    float4 xv[EPT], lv[EPT];
    #pragma unroll
    for (int j = 0; j < EPT; j++) xv[j] = __ldcs(&b4[tid + j * TPB]);
    #pragma unroll
    for (int j = 0; j < EPT; j++) lv[j] = __ldcs(&l4[tid + j * TPB]);

    // labels are exactly 0.0f/1.0f: bit 29 of the fp32 pattern distinguishes them.
    // Collapse 16 label floats into one 16-bit mask (frees 15 registers).
    unsigned mask = 0u;
    #pragma unroll
    for (int j = 0; j < EPT; j++) {
        const float fs[4] = {lv[j].x, lv[j].y, lv[j].z, lv[j].w};
        #pragma unroll
        for (int e = 0; e < 4; e++)
            mask |= ((__float_as_uint(fs[e]) >> 29) & 1u) << (4 * j + e);
    }
    const int npos_own = __popc(mask);      // this thread's positive count

    float accA[NLVL];
    #pragma unroll
    for (int l = 0; l < NLVL; l++) accA[l] = 0.f;
    float accP = 0.f;                       // lane L (<10): warp-total H_pos level L
    const float lvladd = (float)(lane - 4);

    #pragma unroll
    for (int j = 0; j < EPT; j++) {
        float xs[4] = {xv[j].x, xv[j].y, xv[j].z, xv[j].w};
        #pragma unroll
        for (int e = 0; e < 4; e++) {
            const float x = xs[e];
            // u[L] = clamp((L+1)-t, 0, 1) = sat(5x + (L-4)),  t = 5 - 5x
            #pragma unroll
            for (int l = 0; l < NLVL; l++) {
                float u = ffma_sat5(x, (float)(l - 4));
                facc1(accA[l], u);
            }
            // positives ~1/64 dense: per set bit, one histogram level per lane
            unsigned m = __ballot_sync(0xffffffffu, (mask & (1u << (4 * j + e))) != 0u);
            while (m) {
                const int src = __ffs(m) - 1;
                m &= m - 1u;
                const float xb = __shfl_sync(0xffffffffu, x, src);
                const float u  = ffma_sat5(xb, lvladd);
                if (lane < NLVL) facc1(accP, u);
            }
        }
    }

    // ---- block reduction: smem two-phase (no long SHFL chains) ----
    __shared__ float sA[NLVL][TPB + 1];     // +1 pad: conflict-free strided reads
    __shared__ float sAp[NLVL][16];
    __shared__ float sP[NWARP][NLVL];
    __shared__ float sNp[NWARP];
    __shared__ float tot[21];

    #pragma unroll
    for (int l = 0; l < NLVL; l++) sA[l][tid] = accA[l];
    if (lane < NLVL) sP[warp][lane] = accP;
    {   // per-warp int reduce of npos (cheap)
        int v = npos_own;
        #pragma unroll
        for (int o = 16; o > 0; o >>= 1) v += __shfl_down_sync(0xffffffffu, v, o);
        if (lane == 0) sNp[warp] = (float)v;
    }
    __syncthreads();

    if (tid < NLVL * 16) {                  // 160 threads: level = tid>>4, chunk = tid&15
        const int l = tid >> 4, c = tid & 15;
        float s = 0.f;
        #pragma unroll
        for (int i = 0; i < 16; i++) s += sA[l][c + 16 * i];
        sAp[l][c] = s;
    } else if (tid < NLVL * 16 + NLVL) {    // 10 threads: H_pos totals
        const int l = tid - NLVL * 16;
        float s = 0.f;
        #pragma unroll
        for (int w = 0; w < NWARP; w++) s += sP[w][l];
        tot[10 + l] = s;
    } else if (tid == NLVL * 16 + NLVL) {   // 1 thread: npos total
        float s = 0.f;
        #pragma unroll
        for (int w = 0; w < NWARP; w++) s += sNp[w];
        tot[20] = s;
    }
    __syncthreads();

    if (tid < NLVL) {
        float s = 0.f;
        #pragma unroll
        for (int c = 0; c < 16; c++) s += sAp[tid][c];
        tot[tid] = s;
    }
    __syncthreads();

    if (tid == 0) {
        float totA[NLVL + 1], totP[NLVL + 1];
        #pragma unroll
        for (int l = 0; l < NLVL; l++) { totA[l] = tot[l]; totP[l] = tot[10 + l]; }
        const float np = tot[20];
        totA[NLVL] = (float)NROW;   // every element contributes 1 at level 10
        totP[NLVL] = np;

        float apsum = 0.f, prev = 0.f;
        #pragma unroll
        for (int l = 0; l <= NLVL; l++) {
            float h = totP[l] - prev;               // h_pos[l]
            if (totA[l] > 0.f) apsum += h * totP[l] / totA[l];
            prev = totP[l];
        }
        const bool valid = (np > 0.f);
        const float ap = valid ? (apsum / np) : 0.f;

        // ---- fused finalize: last-arriving block computes the scalar loss ----
        atomicAdd(&g_acc_a, ap);
        atomicAdd(&g_acc_v, valid ? 1.f : 0.f);
        __threadfence();
        const unsigned arrived = atomicAdd(&g_cnt, 1u);
        if (arrived == NROW - 1) {
            const float ta = *(volatile float*)&g_acc_a;
            const float tv = *(volatile float*)&g_acc_v;
            out[0] = 1.0f - ta / tv;
            // reset for the next graph replay
            g_acc_a = 0.f;
            g_acc_v = 0.f;
            g_cnt = 0u;
        }
    }
}

extern "C" void kernel_launch(void* const* d_in, const int* in_sizes, int n_in,
                              void* d_out, int out_size)
{
    const float* batch  = (const float*)d_in[0];
    const float* labels = (const float*)d_in[1];
    fastap_fused<<<NROW, TPB>>>(batch, labels, (float*)d_out);
}

// round 9
// speedup vs baseline: 1.6639x; 1.0707x over previous
#include <cuda_runtime.h>
#include <cuda_fp16.h>

#define NROW 4096
#define NLVL 10   // levels L=0..9; level 10 is trivial (H_all=N, H_pos=N_pos)
#define TPB  256
#define EPT  4    // float4 per array per thread: TPB*EPT*4 = 4096
#define NWARP (TPB / 32)

__device__ float g_acc_a = 0.f;
__device__ float g_acc_v = 0.f;
__device__ unsigned int g_cnt = 0u;

// u = sat(x*5 + addend)  -- FFMA with immediate multiplier (rt=1) + SAT (fp32, pos path)
__device__ __forceinline__ float ffma_sat5(float x, float addend) {
    float u;
    asm("fma.rn.sat.f32 %0, %1, 0f40A00000, %2;" : "=f"(u) : "f"(x), "f"(addend));
    return u;
}
// acc = u*1.0 + acc  -- FFMA-imm (rt=1)
__device__ __forceinline__ void facc1(float& acc, float u) {
    asm("fma.rn.f32 %0, %1, 0f3F800000, %0;" : "+f"(acc) : "f"(u));
}

__global__ __launch_bounds__(TPB, 6) void fastap_fused(
    const float* __restrict__ batch, const float* __restrict__ labels,
    float* __restrict__ out)
{
    const int tid  = threadIdx.x;
    const int lane = tid & 31;
    const int warp = tid >> 5;
    const int row  = blockIdx.x;
    const float4* b4 = reinterpret_cast<const float4*>(batch  + (size_t)row * NROW);
    const float4* l4 = reinterpret_cast<const float4*>(labels + (size_t)row * NROW);

    // front-batch all 8 LDG.128
    float4 xv[EPT], lv[EPT];
    #pragma unroll
    for (int j = 0; j < EPT; j++) xv[j] = __ldcs(&b4[tid + j * TPB]);
    #pragma unroll
    for (int j = 0; j < EPT; j++) lv[j] = __ldcs(&l4[tid + j * TPB]);

    // labels are exactly 0.0f/1.0f: bit 29 of the fp32 pattern distinguishes them.
    unsigned mask = 0u;
    #pragma unroll
    for (int j = 0; j < EPT; j++) {
        const float fs[4] = {lv[j].x, lv[j].y, lv[j].z, lv[j].w};
        #pragma unroll
        for (int e = 0; e < 4; e++)
            mask |= ((__float_as_uint(fs[e]) >> 29) & 1u) << (4 * j + e);
    }
    const int npos_own = __popc(mask);

    // level constants (L-4) as half2, materialized once
    __half2 c2[NLVL];
    #pragma unroll
    for (int l = 0; l < NLVL; l++) c2[l] = __floats2half2_rn((float)(l - 4), (float)(l - 4));
    const __half2 five2 = __floats2half2_rn(5.f, 5.f);

    // fp16x2 SIMD accumulators: per-thread per-level sums <= 16 (exact-int range of fp16);
    // fractional rounding contributes ~1e-4 relative on the block totals.
    __half2 accH[NLVL];
    #pragma unroll
    for (int l = 0; l < NLVL; l++) accH[l] = __floats2half2_rn(0.f, 0.f);

    float accP = 0.f;                        // lane L (<10): warp-total H_pos level L (fp32)
    const float lvladd = (float)(lane - 4);

    #pragma unroll
    for (int j = 0; j < EPT; j++) {
        const float xs[4] = {xv[j].x, xv[j].y, xv[j].z, xv[j].w};
        // convert the 4 elements to two half2 pairs up front
        __half2 h2p[2];
        h2p[0] = __floats2half2_rn(xs[0], xs[1]);
        h2p[1] = __floats2half2_rn(xs[2], xs[3]);
        #pragma unroll
        for (int p = 0; p < 2; p++) {        // element pairs
            // u[L] = sat(5x + (L-4)) for both elements at once
            #pragma unroll
            for (int l = 0; l < NLVL; l++)
                accH[l] = __hadd2(accH[l], __hfma2_sat(h2p[p], five2, c2[l]));
            // positives ~1/64 dense: per set bit, one histogram level per lane (fp32)
            #pragma unroll
            for (int e2 = 0; e2 < 2; e2++) {
                const int k = 4 * j + 2 * p + e2;
                const float x = xs[2 * p + e2];
                unsigned m = __ballot_sync(0xffffffffu, (mask & (1u << k)) != 0u);
                while (m) {
                    const int src = __ffs(m) - 1;
                    m &= m - 1u;
                    const float xb = __shfl_sync(0xffffffffu, x, src);
                    const float u  = ffma_sat5(xb, lvladd);
                    if (lane < NLVL) facc1(accP, u);
                }
            }
        }
    }

    // unpack fp16x2 accumulators to fp32 per-level sums
    float accA[NLVL];
    #pragma unroll
    for (int l = 0; l < NLVL; l++)
        accA[l] = __low2float(accH[l]) + __high2float(accH[l]);

    // ---- block reduction: smem two-phase ----
    __shared__ float sA[NLVL][TPB + 1];
    __shared__ float sAp[NLVL][16];
    __shared__ float sP[NWARP][NLVL];
    __shared__ float sNp[NWARP];
    __shared__ float tot[21];

    #pragma unroll
    for (int l = 0; l < NLVL; l++) sA[l][tid] = accA[l];
    if (lane < NLVL) sP[warp][lane] = accP;
    {
        int v = npos_own;
        #pragma unroll
        for (int o = 16; o > 0; o >>= 1) v += __shfl_down_sync(0xffffffffu, v, o);
        if (lane == 0) sNp[warp] = (float)v;
    }
    __syncthreads();

    if (tid < NLVL * 16) {                  // 160 threads: level = tid>>4, chunk = tid&15
        const int l = tid >> 4, c = tid & 15;
        float s = 0.f;
        #pragma unroll
        for (int i = 0; i < 16; i++) s += sA[l][c + 16 * i];
        sAp[l][c] = s;
    } else if (tid < NLVL * 16 + NLVL) {    // 10 threads: H_pos totals
        const int l = tid - NLVL * 16;
        float s = 0.f;
        #pragma unroll
        for (int w = 0; w < NWARP; w++) s += sP[w][l];
        tot[10 + l] = s;
    } else if (tid == NLVL * 16 + NLVL) {   // 1 thread: npos total
        float s = 0.f;
        #pragma unroll
        for (int w = 0; w < NWARP; w++) s += sNp[w];
        tot[20] = s;
    }
    __syncthreads();

    if (tid < NLVL) {
        float s = 0.f;
        #pragma unroll
        for (int c = 0; c < 16; c++) s += sAp[tid][c];
        tot[tid] = s;
    }
    __syncthreads();

    if (tid == 0) {
        float totA[NLVL + 1], totP[NLVL + 1];
        #pragma unroll
        for (int l = 0; l < NLVL; l++) { totA[l] = tot[l]; totP[l] = tot[10 + l]; }
        const float np = tot[20];
        totA[NLVL] = (float)NROW;   // every element contributes 1 at level 10
        totP[NLVL] = np;

        float apsum = 0.f, prev = 0.f;
        #pragma unroll
        for (int l = 0; l <= NLVL; l++) {
            float h = totP[l] - prev;               // h_pos[l]
            if (totA[l] > 0.f) apsum += h * totP[l] / totA[l];
            prev = totP[l];
        }
        const bool valid = (np > 0.f);
        const float ap = valid ? (apsum / np) : 0.f;

        // ---- fused finalize: last-arriving block computes the scalar loss ----
        atomicAdd(&g_acc_a, ap);
        atomicAdd(&g_acc_v, valid ? 1.f : 0.f);
        __threadfence();
        const unsigned arrived = atomicAdd(&g_cnt, 1u);
        if (arrived == NROW - 1) {
            const float ta = *(volatile float*)&g_acc_a;
            const float tv = *(volatile float*)&g_acc_v;
            out[0] = 1.0f - ta / tv;
            // reset for the next graph replay
            g_acc_a = 0.f;
            g_acc_v = 0.f;
            g_cnt = 0u;
        }
    }
}

extern "C" void kernel_launch(void* const* d_in, const int* in_sizes, int n_in,
                              void* d_out, int out_size)
{
    const float* batch  = (const float*)d_in[0];
    const float* labels = (const float*)d_in[1];
    fastap_fused<<<NROW, TPB>>>(batch, labels, (float*)d_out);
}